// round 7
// baseline (speedup 1.0000x reference)
#include <cuda_runtime.h>
#include <cuda_bf16.h>
#include <cstdint>

#define NQ 2048
#define NB 8192
#define DIM 32
#define QTILE 64
#define JTILE 128
#define NQT (NQ / QTILE)   // 32
#define NJT (NB / JTILE)   // 64

// ---------------- device scratch (no allocs allowed) ----------------
__device__ float g_part[(size_t)NQ * NJT * 2];   // [q][jt]{ksum, kysum}

// ---------------- smem layout (bytes) ----------------
// A/B tiles: row-per-point, 144-B stride (64 bf16 = hi[32] | lo[32] = 128 B + 16 pad)
#define ROWB 144
#define SRSTRIDE 528                      // r tile row stride (128 floats + pad)
#define SA 0
#define SB (SA + QTILE * ROWB)            // 9216
#define SR (SB + JTILE * ROWB)            // 27648
#define SY (SR + QTILE * SRSTRIDE)       // 61440
#define SQ2 (SY + 512)                    // 61952
#define SB2 (SQ2 + 256)                   // 62208
#define SPART (SB2 + 512)                 // 62720
#define SM_SIZE (SPART + QTILE * 4 * 8)   // 64768 (~63.2 KB -> 3 CTAs/SM)

// ---------------- asm helpers ----------------
#define SQRTA(d, x)  asm("sqrt.approx.ftz.f32 %0, %1;" : "=f"(d) : "f"(x))
#define EX2A(d, x)   asm("ex2.approx.ftz.f32 %0, %1;"  : "=f"(d) : "f"(x))
#define CP16(dst, src) asm volatile("cp.async.cg.shared.global [%0], [%1], 16;" :: "r"(dst), "l"(src))
#define CP_COMMIT()  asm volatile("cp.async.commit_group;")
#define CP_WAIT0()   asm volatile("cp.async.wait_group 0;")

__device__ __forceinline__ uint32_t smem_u32(const void* p) {
    uint32_t a;
    asm("{ .reg .u64 t; cvta.to.shared.u64 t, %1; cvt.u32.u64 %0, t; }" : "=r"(a) : "l"(p));
    return a;
}

#define LDSM_X4(r0, r1, r2, r3, addr)                                              \
    asm volatile("ldmatrix.sync.aligned.m8n8.x4.shared.b16 {%0,%1,%2,%3}, [%4];"   \
        : "=r"(r0), "=r"(r1), "=r"(r2), "=r"(r3) : "r"(addr))

#define MMA16816(d, a, b0, b1)                                                     \
    asm volatile("mma.sync.aligned.m16n8k16.row.col.f32.bf16.bf16.f32 "            \
        "{%0,%1,%2,%3}, {%4,%5,%6,%7}, {%8,%9}, {%0,%1,%2,%3};"                    \
        : "+f"((d)[0]), "+f"((d)[1]), "+f"((d)[2]), "+f"((d)[3])                   \
        : "r"((a)[0]), "r"((a)[1]), "r"((a)[2]), "r"((a)[3]), "r"(b0), "r"(b1))

// weighted hi/lo bf16 split of 16 coords -> smem row (hi at +0, lo at +64), + sumsq
__device__ __forceinline__ float split16(const float* __restrict__ src,
                                         const float* __restrict__ wv,
                                         char* dst) {
    float x[16];
    #pragma unroll
    for (int i = 0; i < 4; ++i) {
        float4 v = *(const float4*)&src[i * 4];
        x[i*4+0] = v.x * wv[i*4+0]; x[i*4+1] = v.y * wv[i*4+1];
        x[i*4+2] = v.z * wv[i*4+2]; x[i*4+3] = v.w * wv[i*4+3];
    }
    float s = 0.f;
    uint32_t h32[8], l32[8];
    #pragma unroll
    for (int i = 0; i < 8; ++i) {
        float x0 = x[2*i], x1 = x[2*i+1];
        __nv_bfloat16 h0 = __float2bfloat16(x0);
        __nv_bfloat16 h1 = __float2bfloat16(x1);
        float r0 = x0 - __bfloat162float(h0);
        float r1 = x1 - __bfloat162float(h1);
        __nv_bfloat162 hp = __halves2bfloat162(h0, h1);
        __nv_bfloat162 lp = __halves2bfloat162(__float2bfloat16(r0), __float2bfloat16(r1));
        h32[i] = *(uint32_t*)&hp;
        l32[i] = *(uint32_t*)&lp;
        s = fmaf(x0, x0, fmaf(x1, x1, s));
    }
    *(uint4*)(dst +  0) = make_uint4(h32[0], h32[1], h32[2], h32[3]);
    *(uint4*)(dst + 16) = make_uint4(h32[4], h32[5], h32[6], h32[7]);
    *(uint4*)(dst + 64) = make_uint4(l32[0], l32[1], l32[2], l32[3]);
    *(uint4*)(dst + 80) = make_uint4(l32[4], l32[5], l32[6], l32[7]);
    return s;
}

// ---------------- main: HMMA GEMM + fused epilogue ----------------
// grid (NQT=32, NJT=64) = 2048 CTAs, block 256 (8 warps), 3 CTAs/SM.
// warp = (wq 0..1) x (wj 0..3): 32q x 32j per warp; 2 m-tiles x 4 n-tiles m16n8k16.
__global__ __launch_bounds__(256, 3) void nw_main(
    const float* __restrict__ xb,
    const float* __restrict__ xq,
    const float* __restrict__ w,
    const float* __restrict__ yb,
    const float* __restrict__ r,
    const float* __restrict__ sigma,
    const float* __restrict__ r_scale)
{
    extern __shared__ __align__(16) char smem_raw[];
    const uint32_t sbase = smem_u32(smem_raw);

    const int tid  = threadIdx.x;
    const int lane = tid & 31;
    const int warp = tid >> 5;
    const int wq   = warp >> 2;          // 0..1
    const int wj   = warp & 3;           // 0..3
    const int qt   = blockIdx.x;
    const int jt   = blockIdx.y;
    const int jb   = jt * JTILE;
    const int qb   = qt * QTILE;

    // ---- kick off r tile + y stream (cp.async, one group) ----
    // thread t owns row t>>2, quarter t&3 (8 x 16B chunks)
    {
        const int row = tid >> 2;
        const int c4  = tid & 3;
        const char* src = (const char*)&r[(size_t)(qb + row) * NB + jb] + c4 * 128;
        const uint32_t dst = sbase + SR + row * SRSTRIDE + c4 * 128;
        #pragma unroll
        for (int i = 0; i < 8; ++i)
            CP16(dst + i * 16, src + i * 16);
    }
    if (tid < 32)
        CP16(sbase + SY + tid * 16, (const char*)&yb[jb] + tid * 16);
    CP_COMMIT();

    // ---- in-block weighted hi/lo split of A (query) and B (backgnd) tiles ----
    {
        const int row = tid >> 1;        // 0..127
        const int hl  = tid & 1;
        float wv[16];
        #pragma unroll
        for (int i = 0; i < 4; ++i)
            *(float4*)&wv[i * 4] = *(const float4*)&w[hl * 16 + i * 4];

        float sB = split16(xb + (size_t)(jb + row) * DIM + hl * 16, wv,
                           smem_raw + SB + row * ROWB + hl * 32);
        sB += __shfl_xor_sync(0xffffffffu, sB, 1);
        if (hl == 0) ((float*)(smem_raw + SB2))[row] = sB;

        if (row < QTILE) {
            float sA = split16(xq + (size_t)(qb + row) * DIM + hl * 16, wv,
                               smem_raw + SA + row * ROWB + hl * 32);
            sA += __shfl_xor_sync(0xffffffffu, sA, 1);
            if (hl == 0) ((float*)(smem_raw + SQ2))[row] = sA;
        }
    }

    const float L2E = 1.4426950408889634f;
    const float crf = r_scale[0] * L2E;
    const float cdf = -L2E / sigma[0];

    __syncthreads();   // A/B/q2/b2 tiles ready

    // ---- HMMA phase: D = Ahi.Bhi + Ahi.Blo + Alo.Bhi over K=32 ----
    float d[2][4][4];
    #pragma unroll
    for (int mt = 0; mt < 2; ++mt)
        #pragma unroll
        for (int nt = 0; nt < 4; ++nt)
            #pragma unroll
            for (int i = 0; i < 4; ++i) d[mt][nt][i] = 0.f;

    const uint32_t arow = sbase + SA + (uint32_t)(wq * 32 + (lane & 15)) * ROWB
                        + ((lane >> 4) & 1) * 16;
    const uint32_t brow = sbase + SB
                        + (uint32_t)(wj * 32 + ((lane >> 4) << 3) + (lane & 7)) * ROWB
                        + ((lane >> 3) & 1) * 16;

    const int AOFF[6] = { 0, 32, 0, 32, 64, 96 };    // hi0 hi1 hi0 hi1 lo0 lo1
    const int BOFF[6] = { 0, 32, 64, 96, 0, 32 };    // hi0 hi1 lo0 lo1 hi0 hi1

    #pragma unroll
    for (int c = 0; c < 6; ++c) {
        uint32_t a[2][4], b[2][4];
        LDSM_X4(a[0][0], a[0][1], a[0][2], a[0][3], arow + AOFF[c]);
        LDSM_X4(a[1][0], a[1][1], a[1][2], a[1][3], arow + 16 * ROWB + AOFF[c]);
        #pragma unroll
        for (int p = 0; p < 2; ++p)
            LDSM_X4(b[p][0], b[p][1], b[p][2], b[p][3], brow + p * 16 * ROWB + BOFF[c]);
        #pragma unroll
        for (int mt = 0; mt < 2; ++mt)
            #pragma unroll
            for (int nt = 0; nt < 4; ++nt)
                MMA16816(d[mt][nt], a[mt], b[nt >> 1][(nt & 1) * 2], b[nt >> 1][(nt & 1) * 2 + 1]);
    }

    CP_WAIT0();        // r + y arrived (own chunks), barrier publishes all
    __syncthreads();

    // ---- epilogue: dist, exp, accumulate (all smem) ----
    const int g = lane >> 2;
    const int t = lane & 3;

    float q2r[4];
    #pragma unroll
    for (int mt = 0; mt < 2; ++mt)
        #pragma unroll
        for (int h = 0; h < 2; ++h)
            q2r[mt * 2 + h] = ((const float*)(smem_raw + SQ2))[wq * 32 + mt * 16 + g + 8 * h];

    float ks[4] = {0.f, 0.f, 0.f, 0.f}, ky[4] = {0.f, 0.f, 0.f, 0.f};

    #pragma unroll
    for (int nt = 0; nt < 4; ++nt) {
        const int jo = wj * 32 + nt * 8 + 2 * t;
        float2 b2p = *(const float2*)(smem_raw + SB2 + jo * 4);
        float2 yp  = *(const float2*)(smem_raw + SY  + jo * 4);
        #pragma unroll
        for (int mt = 0; mt < 2; ++mt) {
            #pragma unroll
            for (int h = 0; h < 2; ++h) {
                const int idx = mt * 2 + h;
                const int qr = wq * 32 + mt * 16 + g + 8 * h;
                float2 rv = *(const float2*)(smem_raw + SR + qr * SRSTRIDE + jo * 4);
                float dot0 = d[mt][nt][h * 2 + 0];
                float dot1 = d[mt][nt][h * 2 + 1];
                float base = q2r[idx];

                float d20 = fmaf(-2.f, dot0, base + b2p.x);
                float d21 = fmaf(-2.f, dot1, base + b2p.y);
                d20 = fmaxf(d20, 0.f);
                d21 = fmaxf(d21, 0.f);
                float ds0, ds1;
                SQRTA(ds0, d20);
                SQRTA(ds1, d21);
                float lg0 = fmaf(cdf, ds0, crf * rv.x);
                float lg1 = fmaf(cdf, ds1, crf * rv.y);
                float k0, k1;
                EX2A(k0, lg0);
                EX2A(k1, lg1);
                ks[idx] += k0 + k1;
                ky[idx] = fmaf(k0, yp.x, fmaf(k1, yp.y, ky[idx]));
            }
        }
    }

    // reduce across the 4 t-lanes; one owner per (qr, wj)
    #pragma unroll
    for (int idx = 0; idx < 4; ++idx) {
        float a = ks[idx], b = ky[idx];
        a += __shfl_xor_sync(0xffffffffu, a, 1);
        b += __shfl_xor_sync(0xffffffffu, b, 1);
        a += __shfl_xor_sync(0xffffffffu, a, 2);
        b += __shfl_xor_sync(0xffffffffu, b, 2);
        if (t == 0) {
            const int mt = idx >> 1, h = idx & 1;
            const int qr = wq * 32 + mt * 16 + g + 8 * h;
            *(float2*)(smem_raw + SPART + (qr * 4 + wj) * 8) = make_float2(a, b);
        }
    }
    __syncthreads();

    if (tid < QTILE) {
        float2 acc = make_float2(0.f, 0.f);
        #pragma unroll
        for (int j = 0; j < 4; ++j) {
            float2 v = *(const float2*)(smem_raw + SPART + (tid * 4 + j) * 8);
            acc.x += v.x;
            acc.y += v.y;
        }
        *(float2*)&g_part[((size_t)(qb + tid) * NJT + jt) * 2] = acc;
    }
}

// ---------------- final reduce: one warp per query ----------------
__global__ void nw_reduce(float* __restrict__ out) {
    const int q    = (blockIdx.x * 256 + threadIdx.x) >> 5;
    const int lane = threadIdx.x & 31;
    const float2* p = (const float2*)&g_part[(size_t)q * NJT * 2];
    float2 v0 = p[lane];
    float2 v1 = p[lane + 32];
    float ks = v0.x + v1.x;
    float ky = v0.y + v1.y;
    #pragma unroll
    for (int off = 16; off; off >>= 1) {
        ks += __shfl_xor_sync(0xffffffffu, ks, off);
        ky += __shfl_xor_sync(0xffffffffu, ky, off);
    }
    if (lane == 0) out[q] = ky / (ks + 1e-8f);
}

// ---------------- launch ----------------
extern "C" void kernel_launch(void* const* d_in, const int* in_sizes, int n_in,
                              void* d_out, int out_size) {
    (void)in_sizes; (void)n_in; (void)out_size;
    const float* x_backgnd = (const float*)d_in[0];
    const float* y_backgnd = (const float*)d_in[1];
    const float* x_query   = (const float*)d_in[2];
    const float* r         = (const float*)d_in[3];
    const float* sigma     = (const float*)d_in[4];
    const float* r_scale   = (const float*)d_in[5];
    const float* w         = (const float*)d_in[6];
    float* out = (float*)d_out;

    cudaFuncSetAttribute(nw_main, cudaFuncAttributeMaxDynamicSharedMemorySize, SM_SIZE);

    nw_main<<<dim3(NQT, NJT), 256, SM_SIZE>>>(x_backgnd, x_query, w,
                                              y_backgnd, r, sigma, r_scale);
    nw_reduce<<<(NQ * 32) / 256, 256>>>(out);
}

// round 10
// speedup vs baseline: 1.0623x; 1.0623x over previous
#include <cuda_runtime.h>
#include <cuda_bf16.h>
#include <cstdint>

#define NQ 2048
#define NB 8192
#define DIM 32
#define QTILE 128
#define JTILE 128
#define NQT (NQ / QTILE)   // 16
#define NJT (NB / JTILE)   // 64

// ---------------- device scratch (no allocs allowed) ----------------
__device__ float g_part[(size_t)NQ * NJT * 2];   // [q][jt]{ksum, kysum}
__device__ unsigned int g_ticket[NQT];           // zero-init; reset in-kernel

// ---------------- smem layout (bytes) ----------------
#define ROWB 144
#define SRSTRIDE 528
#define SA 0
#define SB (SA + QTILE * ROWB)            // 18432
#define SR (SB + JTILE * ROWB)            // 36864
#define SY (SR + QTILE * SRSTRIDE)       // 104448
#define SQ2 (SY + 512)                    // 104960
#define SB2 (SQ2 + 512)                   // 105472
#define SPART (SB2 + 512)                 // 105984
#define SFLAG (SPART + 2048)              // 108032
#define SM_SIZE (SFLAG + 16)              // 108048

// ---------------- asm helpers ----------------
#define SQRTA(d, x)  asm("sqrt.approx.ftz.f32 %0, %1;" : "=f"(d) : "f"(x))
#define EX2A(d, x)   asm("ex2.approx.ftz.f32 %0, %1;"  : "=f"(d) : "f"(x))
#define CP16(dst, src) asm volatile("cp.async.cg.shared.global [%0], [%1], 16;" :: "r"(dst), "l"(src))
#define CP_COMMIT()  asm volatile("cp.async.commit_group;")
#define CP_WAIT0()   asm volatile("cp.async.wait_group 0;")

__device__ __forceinline__ uint32_t smem_u32(const void* p) {
    uint32_t a;
    asm("{ .reg .u64 t; cvta.to.shared.u64 t, %1; cvt.u32.u64 %0, t; }" : "=r"(a) : "l"(p));
    return a;
}

#define LDSM_X4(r0, r1, r2, r3, addr)                                              \
    asm volatile("ldmatrix.sync.aligned.m8n8.x4.shared.b16 {%0,%1,%2,%3}, [%4];"   \
        : "=r"(r0), "=r"(r1), "=r"(r2), "=r"(r3) : "r"(addr))

#define MMA16816(d, a, b0, b1)                                                     \
    asm volatile("mma.sync.aligned.m16n8k16.row.col.f32.bf16.bf16.f32 "            \
        "{%0,%1,%2,%3}, {%4,%5,%6,%7}, {%8,%9}, {%0,%1,%2,%3};"                    \
        : "+f"((d)[0]), "+f"((d)[1]), "+f"((d)[2]), "+f"((d)[3])                   \
        : "r"((a)[0]), "r"((a)[1]), "r"((a)[2]), "r"((a)[3]), "r"(b0), "r"(b1))

// weighted hi/lo bf16 split of 16 coords -> smem row (hi at +0, lo at +64), + sumsq
__device__ __forceinline__ float split16(const float* __restrict__ src,
                                         const float* __restrict__ wv,
                                         char* dst) {
    float x[16];
    #pragma unroll
    for (int i = 0; i < 4; ++i) {
        float4 v = *(const float4*)&src[i * 4];
        x[i*4+0] = v.x * wv[i*4+0]; x[i*4+1] = v.y * wv[i*4+1];
        x[i*4+2] = v.z * wv[i*4+2]; x[i*4+3] = v.w * wv[i*4+3];
    }
    float s = 0.f;
    uint32_t h32[8], l32[8];
    #pragma unroll
    for (int i = 0; i < 8; ++i) {
        float x0 = x[2*i], x1 = x[2*i+1];
        __nv_bfloat16 h0 = __float2bfloat16(x0);
        __nv_bfloat16 h1 = __float2bfloat16(x1);
        float r0 = x0 - __bfloat162float(h0);
        float r1 = x1 - __bfloat162float(h1);
        __nv_bfloat162 hp = __halves2bfloat162(h0, h1);
        __nv_bfloat162 lp = __halves2bfloat162(__float2bfloat16(r0), __float2bfloat16(r1));
        h32[i] = *(uint32_t*)&hp;
        l32[i] = *(uint32_t*)&lp;
        s = fmaf(x0, x0, fmaf(x1, x1, s));
    }
    *(uint4*)(dst +  0) = make_uint4(h32[0], h32[1], h32[2], h32[3]);
    *(uint4*)(dst + 16) = make_uint4(h32[4], h32[5], h32[6], h32[7]);
    *(uint4*)(dst + 64) = make_uint4(l32[0], l32[1], l32[2], l32[3]);
    *(uint4*)(dst + 80) = make_uint4(l32[4], l32[5], l32[6], l32[7]);
    return s;
}

// ---------------- fused main: HMMA GEMM + epilogue + last-CTA reduce ----------------
// grid (NQT=16, NJT=64) = 1024 CTAs, block 256 (8 warps), 2 CTAs/SM.
// warp = (wq 0..3) x (wj 0..1): 32q x 64j per warp; 2 m-tiles x 8 n-tiles m16n8k16.
__global__ __launch_bounds__(256, 2) void nw_main(
    const float* __restrict__ xb,
    const float* __restrict__ xq,
    const float* __restrict__ w,
    const float* __restrict__ yb,
    const float* __restrict__ r,
    const float* __restrict__ sigma,
    const float* __restrict__ r_scale,
    float* __restrict__ out)
{
    extern __shared__ __align__(16) char smem_raw[];
    const uint32_t sbase = smem_u32(smem_raw);

    const int tid  = threadIdx.x;
    const int lane = tid & 31;
    const int warp = tid >> 5;
    const int wq   = warp >> 1;          // 0..3
    const int wj   = warp & 1;           // 0..1
    const int qt   = blockIdx.x;
    const int jt   = blockIdx.y;
    const int jb   = jt * JTILE;
    const int qb   = qt * QTILE;

    // ---- kick off r tile + y stream (cp.async, one group) ----
    #pragma unroll
    for (int i = 0; i < 16; ++i) {
        int e = tid + 256 * i;           // 4096 chunks of 16B
        int row = e >> 5;
        int c = e & 31;
        CP16(sbase + SR + row * SRSTRIDE + c * 16,
             (const char*)&r[(size_t)(qb + row) * NB + jb + c * 4]);
    }
    if (tid < 32)
        CP16(sbase + SY + tid * 16, (const char*)&yb[jb] + tid * 16);
    CP_COMMIT();

    // ---- in-block weighted hi/lo split of A (query) and B (backgnd) tiles ----
    {
        const int row = tid >> 1;
        const int hl  = tid & 1;
        float wv[16];
        #pragma unroll
        for (int i = 0; i < 4; ++i)
            *(float4*)&wv[i * 4] = *(const float4*)&w[hl * 16 + i * 4];

        float sA = split16(xq + (size_t)(qb + row) * DIM + hl * 16, wv,
                           smem_raw + SA + row * ROWB + hl * 32);
        float sB = split16(xb + (size_t)(jb + row) * DIM + hl * 16, wv,
                           smem_raw + SB + row * ROWB + hl * 32);
        sA += __shfl_xor_sync(0xffffffffu, sA, 1);
        sB += __shfl_xor_sync(0xffffffffu, sB, 1);
        if (hl == 0) {
            ((float*)(smem_raw + SQ2))[row] = sA;
            ((float*)(smem_raw + SB2))[row] = sB;
        }
    }

    const float L2E = 1.4426950408889634f;
    const float crf = r_scale[0] * L2E;
    const float cdf = -L2E / sigma[0];

    __syncthreads();   // A/B/q2/b2 tiles ready

    // ---- HMMA phase: D = Ahi.Bhi + Ahi.Blo + Alo.Bhi over K=32 ----
    float d[2][8][4];
    #pragma unroll
    for (int mt = 0; mt < 2; ++mt)
        #pragma unroll
        for (int nt = 0; nt < 8; ++nt)
            #pragma unroll
            for (int i = 0; i < 4; ++i) d[mt][nt][i] = 0.f;

    const uint32_t arow = sbase + SA + (uint32_t)(wq * 32 + (lane & 15)) * ROWB
                        + ((lane >> 4) & 1) * 16;
    const uint32_t brow = sbase + SB
                        + (uint32_t)(wj * 64 + ((lane >> 4) << 3) + (lane & 7)) * ROWB
                        + ((lane >> 3) & 1) * 16;

    const int AOFF[6] = { 0, 32, 0, 32, 64, 96 };    // hi0 hi1 hi0 hi1 lo0 lo1
    const int BOFF[6] = { 0, 32, 64, 96, 0, 32 };    // hi0 hi1 lo0 lo1 hi0 hi1

    #pragma unroll
    for (int c = 0; c < 6; ++c) {
        uint32_t a[2][4], b[4][4];
        LDSM_X4(a[0][0], a[0][1], a[0][2], a[0][3], arow + AOFF[c]);
        LDSM_X4(a[1][0], a[1][1], a[1][2], a[1][3], arow + 16 * ROWB + AOFF[c]);
        #pragma unroll
        for (int p = 0; p < 4; ++p)
            LDSM_X4(b[p][0], b[p][1], b[p][2], b[p][3], brow + p * 16 * ROWB + BOFF[c]);
        #pragma unroll
        for (int mt = 0; mt < 2; ++mt)
            #pragma unroll
            for (int nt = 0; nt < 8; ++nt)
                MMA16816(d[mt][nt], a[mt], b[nt >> 1][(nt & 1) * 2], b[nt >> 1][(nt & 1) * 2 + 1]);
    }

    CP_WAIT0();        // r + y arrived
    __syncthreads();

    // ---- epilogue: dist, exp, accumulate (all smem) ----
    const int g = lane >> 2;
    const int t = lane & 3;

    float q2r[4];
    #pragma unroll
    for (int mt = 0; mt < 2; ++mt)
        #pragma unroll
        for (int h = 0; h < 2; ++h)
            q2r[mt * 2 + h] = ((const float*)(smem_raw + SQ2))[wq * 32 + mt * 16 + g + 8 * h];

    float ks[4] = {0.f, 0.f, 0.f, 0.f}, ky[4] = {0.f, 0.f, 0.f, 0.f};

    #pragma unroll
    for (int nt = 0; nt < 8; ++nt) {
        const int jo = wj * 64 + nt * 8 + 2 * t;
        float2 b2p = *(const float2*)(smem_raw + SB2 + jo * 4);
        float2 yp  = *(const float2*)(smem_raw + SY  + jo * 4);
        #pragma unroll
        for (int mt = 0; mt < 2; ++mt) {
            #pragma unroll
            for (int h = 0; h < 2; ++h) {
                const int idx = mt * 2 + h;
                const int qr = wq * 32 + mt * 16 + g + 8 * h;
                float2 rv = *(const float2*)(smem_raw + SR + qr * SRSTRIDE + jo * 4);
                float dot0 = d[mt][nt][h * 2 + 0];
                float dot1 = d[mt][nt][h * 2 + 1];
                float base = q2r[idx];

                float d20 = fmaf(-2.f, dot0, base + b2p.x);
                float d21 = fmaf(-2.f, dot1, base + b2p.y);
                d20 = fmaxf(d20, 0.f);
                d21 = fmaxf(d21, 0.f);
                float ds0, ds1;
                SQRTA(ds0, d20);
                SQRTA(ds1, d21);
                float lg0 = fmaf(cdf, ds0, crf * rv.x);
                float lg1 = fmaf(cdf, ds1, crf * rv.y);
                float k0, k1;
                EX2A(k0, lg0);
                EX2A(k1, lg1);
                ks[idx] += k0 + k1;
                ky[idx] = fmaf(k0, yp.x, fmaf(k1, yp.y, ky[idx]));
            }
        }
    }

    // reduce across the 4 t-lanes; one owner per (qr, wj)
    #pragma unroll
    for (int idx = 0; idx < 4; ++idx) {
        float a = ks[idx], b = ky[idx];
        a += __shfl_xor_sync(0xffffffffu, a, 1);
        b += __shfl_xor_sync(0xffffffffu, b, 1);
        a += __shfl_xor_sync(0xffffffffu, a, 2);
        b += __shfl_xor_sync(0xffffffffu, b, 2);
        if (t == 0) {
            const int mt = idx >> 1, h = idx & 1;
            const int qr = wq * 32 + mt * 16 + g + 8 * h;
            *(float2*)(smem_raw + SPART + (qr * 2 + wj) * 8) = make_float2(a, b);
        }
    }
    __syncthreads();

    if (tid < 128) {
        float2 a = *(const float2*)(smem_raw + SPART + (tid * 2 + 0) * 8);
        float2 b = *(const float2*)(smem_raw + SPART + (tid * 2 + 1) * 8);
        *(float2*)&g_part[((size_t)(qb + tid) * NJT + jt) * 2] =
            make_float2(a.x + b.x, a.y + b.y);
    }
    __syncthreads();

    // ---- last-CTA-per-qt final reduction (deterministic: fixed read order) ----
    if (tid == 0) {
        __threadfence();
        unsigned int old = atomicAdd(&g_ticket[qt], 1u);
        *(volatile unsigned int*)(smem_raw + SFLAG) = (old == NJT - 1) ? 1u : 0u;
    }
    __syncthreads();
    if (*(volatile unsigned int*)(smem_raw + SFLAG)) {
        __threadfence();   // acquire partials written by other CTAs
        // warp-per-query, 16 queries per warp, all loads issued up front
        const int q0 = qb + warp;
        float2 v0[16], v1[16];
        #pragma unroll
        for (int i = 0; i < 16; ++i) {
            const float2* p = (const float2*)&g_part[(size_t)(q0 + i * 8) * NJT * 2];
            v0[i] = p[lane];
            v1[i] = p[lane + 32];
        }
        #pragma unroll
        for (int i = 0; i < 16; ++i) {
            float kss = v0[i].x + v1[i].x;
            float kys = v0[i].y + v1[i].y;
            #pragma unroll
            for (int off = 16; off; off >>= 1) {
                kss += __shfl_xor_sync(0xffffffffu, kss, off);
                kys += __shfl_xor_sync(0xffffffffu, kys, off);
            }
            if (lane == 0) out[q0 + i * 8] = kys / (kss + 1e-8f);
        }
        if (tid == 0) g_ticket[qt] = 0;   // reset for next graph replay
    }
}

// ---------------- launch ----------------
extern "C" void kernel_launch(void* const* d_in, const int* in_sizes, int n_in,
                              void* d_out, int out_size) {
    (void)in_sizes; (void)n_in; (void)out_size;
    const float* x_backgnd = (const float*)d_in[0];
    const float* y_backgnd = (const float*)d_in[1];
    const float* x_query   = (const float*)d_in[2];
    const float* r         = (const float*)d_in[3];
    const float* sigma     = (const float*)d_in[4];
    const float* r_scale   = (const float*)d_in[5];
    const float* w         = (const float*)d_in[6];
    float* out = (float*)d_out;

    cudaFuncSetAttribute(nw_main, cudaFuncAttributeMaxDynamicSharedMemorySize, SM_SIZE);

    nw_main<<<dim3(NQT, NJT), 256, SM_SIZE>>>(x_backgnd, x_query, w,
                                              y_backgnd, r, sigma, r_scale, out);
}